// round 15
// baseline (speedup 1.0000x reference)
#include <cuda_runtime.h>
#include <cuda_bf16.h>
#include <cstdint>
#include <math.h>

#define SEQ 4096
#define H 2048
#define IN_DIM 2048
#define G3 6144

// ---------------- scratch ---------------------------------------------------
__device__ float g_igates[(size_t)SEQ * G3];   // ~100.7 MB
__device__ unsigned int g_bar;                 // root counter (single line)
__device__ unsigned int g_grp[16 * 32];        // 16 group counters, padded lines

__global__ void init_bar_kernel() {
    g_bar = 0u;
    for (int i = 0; i < 16; i++) g_grp[i * 32] = 0u;
}

// ---------------- tf32 mma helpers ------------------------------------------
__device__ __forceinline__ unsigned f2tf32(float f) {
    unsigned u;
    asm("cvt.rna.tf32.f32 %0, %1;" : "=r"(u) : "f"(f));
    return u;
}
__device__ __forceinline__ void mma_tf32(float* c, const unsigned* a,
                                         const unsigned* b) {
    asm volatile(
        "mma.sync.aligned.m16n8k8.row.col.f32.tf32.tf32.f32 "
        "{%0,%1,%2,%3}, {%4,%5,%6,%7}, {%8,%9}, {%0,%1,%2,%3};\n"
        : "+f"(c[0]), "+f"(c[1]), "+f"(c[2]), "+f"(c[3])
        : "r"(a[0]), "r"(a[1]), "r"(a[2]), "r"(a[3]), "r"(b[0]), "r"(b[1]));
}

// ---------------- Kernel 1: igates = xs @ Wi^T + bi (tf32, R13 proven) -----
#define TM 128
#define TN 128
#define TK 16

__global__ __launch_bounds__(256) void igates_gemm(
    const float* __restrict__ A,
    const float* __restrict__ B,
    const float* __restrict__ bias)
{
    __shared__ unsigned As[TM][TK + 1];
    __shared__ unsigned Bs[TN][TK + 1];

    const int tid  = threadIdx.x;
    const int lane = tid & 31;
    const int wid  = tid >> 5;
    const int mw   = wid & 3;
    const int nw   = wid >> 2;
    const int bm   = blockIdx.y * TM;
    const int bn   = blockIdx.x * TN;
    const int grp  = lane >> 2;
    const int tig  = lane & 3;

    float c[16][4];
    #pragma unroll
    for (int i = 0; i < 16; i++)
        #pragma unroll
        for (int j = 0; j < 4; j++) c[i][j] = 0.f;

    for (int k0 = 0; k0 < IN_DIM; k0 += TK) {
        #pragma unroll
        for (int i = 0; i < 2; i++) {
            const int id  = tid + i * 256;
            const int row = id >> 2;
            const int c4  = (id & 3) * 4;
            float4 va = *(const float4*)(A + (size_t)(bm + row) * IN_DIM + k0 + c4);
            As[row][c4 + 0] = f2tf32(va.x);
            As[row][c4 + 1] = f2tf32(va.y);
            As[row][c4 + 2] = f2tf32(va.z);
            As[row][c4 + 3] = f2tf32(va.w);
            float4 vb = *(const float4*)(B + (size_t)(bn + row) * IN_DIM + k0 + c4);
            Bs[row][c4 + 0] = f2tf32(vb.x);
            Bs[row][c4 + 1] = f2tf32(vb.y);
            Bs[row][c4 + 2] = f2tf32(vb.z);
            Bs[row][c4 + 3] = f2tf32(vb.w);
        }
        __syncthreads();

        #pragma unroll
        for (int kk = 0; kk < TK; kk += 8) {
            unsigned af[2][4];
            #pragma unroll
            for (int mi = 0; mi < 2; mi++) {
                const int r = mw * 32 + mi * 16 + grp;
                af[mi][0] = As[r][kk + tig];
                af[mi][1] = As[r + 8][kk + tig];
                af[mi][2] = As[r][kk + tig + 4];
                af[mi][3] = As[r + 8][kk + tig + 4];
            }
            #pragma unroll
            for (int ni = 0; ni < 8; ni++) {
                const int n = nw * 64 + ni * 8 + grp;
                unsigned bf[2];
                bf[0] = Bs[n][kk + tig];
                bf[1] = Bs[n][kk + tig + 4];
                mma_tf32(c[ni], af[0], bf);
                mma_tf32(c[8 + ni], af[1], bf);
            }
        }
        __syncthreads();
    }

    #pragma unroll
    for (int mi = 0; mi < 2; mi++) {
        #pragma unroll
        for (int ni = 0; ni < 8; ni++) {
            const float* cf = c[mi * 8 + ni];
            const int row = bm + mw * 32 + mi * 16 + grp;
            const int col = bn + nw * 64 + ni * 8 + 2 * tig;
            const float b0 = bias[col], b1 = bias[col + 1];
            float2 v01; v01.x = cf[0] + b0; v01.y = cf[1] + b1;
            float2 v23; v23.x = cf[2] + b0; v23.y = cf[3] + b1;
            *(float2*)(g_igates + (size_t)row * G3 + col) = v01;
            *(float2*)(g_igates + (size_t)(row + 8) * G3 + col) = v23;
        }
    }
}

// ---------------- Kernel 2: persistent GRU recurrence ----------------------
// R13 compute (proven) + two-level atomic arrival tree. Every spin is a
// single-fixed-line volatile read (5/5-proven); no scatter-polling.
#define NCTA 128
#define PER 16
#define NROWS 48
#define RTH 256

__device__ __forceinline__ float bf_lo(unsigned w) {
    return __uint_as_float(w << 16);
}
__device__ __forceinline__ float bf_hi(unsigned w) {
    return __uint_as_float(w & 0xFFFF0000u);
}
__device__ __forceinline__ float fsig(float x) {
    return __fdividef(1.f, 1.f + __expf(-x));
}
__device__ __forceinline__ float ftanh(float x) {
    return __fdividef(2.f, 1.f + __expf(-2.f * x)) - 1.f;
}

__global__ __launch_bounds__(RTH, 1) void gru_recur(
    const float* __restrict__ init_state,
    const float* __restrict__ Wh,
    const float* __restrict__ bn,
    float* __restrict__ out)
{
    extern __shared__ float smem[];
    unsigned* wc = (unsigned*)smem;                        // NROWS * H/2 words (192KB)
    float* h_s   = (float*)(wc + (size_t)NROWS * (H/2));   // H floats (8KB)
    float* red   = h_s + H;                                // NROWS floats

    const int tid  = threadIdx.x;
    const int lane = tid & 31;
    const int wid  = tid >> 5;
    const int bid  = blockIdx.x;
    const int base = bid * PER;
    const int r0   = wid * 6;            // this warp's 6 rows
    const int grp  = bid >> 3;           // group of 8 CTAs
    const bool gleader = ((bid & 7) == 0);

    // prologue: convert+cache 48 Wh rows as packed bf16 (lo=elem 2v, hi=2v+1)
    for (int r = 0; r < NROWS; r++) {
        const int gate = r / PER, i = r % PER;
        const float2* src = (const float2*)(Wh + (size_t)(gate * H + base + i) * H);
        unsigned* dst = wc + (size_t)r * (H / 2);
        for (int v = tid; v < H / 2; v += RTH) {
            float2 w = src[v];
            __nv_bfloat162 b2 = __floats2bfloat162_rn(w.x, w.y);
            dst[v] = *(unsigned*)&b2;
        }
    }
    __syncthreads();   // order prologue wc writes vs first-step reads

    float bnv = 0.f, lastv = 0.f;
    if (tid < PER) bnv = bn[base + tid];

    for (int t = 0; t < SEQ; t++) {
        const float* hprev = (t == 0) ? init_state : (out + (size_t)(t - 1) * H);

        // early reads: igates (DRAM); consumed in the epilogue
        float gr = 0.f, gz = 0.f, gn = 0.f;
        if (tid < PER) {
            const float* ig = g_igates + (size_t)t * G3;
            gr = ig[base + tid];
            gz = ig[H + base + tid];
            gn = ig[2 * H + base + tid];
        }

        // ---- stage h_{t-1} into SMEM once per CTA (one 8KB L2 read) ----
        {
            const float4* h4 = (const float4*)hprev;
            float4* d4 = (float4*)h_s;
            d4[tid]       = __ldcg(h4 + tid);
            d4[tid + RTH] = __ldcg(h4 + tid + RTH);
        }
        __syncthreads();

        // ---- copy h from SMEM into registers once per warp ----
        float hreg[64];
        {
            const float4* hs4 = (const float4*)h_s;
            #pragma unroll
            for (int j = 0; j < 8; j++) {
                float4 a = hs4[(j * 32 + lane) * 2 + 0];
                float4 b = hs4[(j * 32 + lane) * 2 + 1];
                hreg[j * 8 + 0] = a.x; hreg[j * 8 + 1] = a.y;
                hreg[j * 8 + 2] = a.z; hreg[j * 8 + 3] = a.w;
                hreg[j * 8 + 4] = b.x; hreg[j * 8 + 5] = b.y;
                hreg[j * 8 + 6] = b.z; hreg[j * 8 + 7] = b.w;
            }
        }

        // ---- 6 dot products per warp (weights from SMEM, h from regs) ----
        #pragma unroll
        for (int r = 0; r < 6; r++) {
            const uint4* wp = (const uint4*)(wc + (size_t)(r0 + r) * (H / 2));
            float s0 = 0.f, s1 = 0.f, s2 = 0.f, s3 = 0.f;
            float s4 = 0.f, s5 = 0.f, s6 = 0.f, s7 = 0.f;
            #pragma unroll
            for (int j = 0; j < 8; j++) {
                uint4 w4 = wp[j * 32 + lane];       // 8 bf16 = h elems [8j..8j+7]
                s0 = fmaf(bf_lo(w4.x), hreg[j * 8 + 0], s0);
                s1 = fmaf(bf_hi(w4.x), hreg[j * 8 + 1], s1);
                s2 = fmaf(bf_lo(w4.y), hreg[j * 8 + 2], s2);
                s3 = fmaf(bf_hi(w4.y), hreg[j * 8 + 3], s3);
                s4 = fmaf(bf_lo(w4.z), hreg[j * 8 + 4], s4);
                s5 = fmaf(bf_hi(w4.z), hreg[j * 8 + 5], s5);
                s6 = fmaf(bf_lo(w4.w), hreg[j * 8 + 6], s6);
                s7 = fmaf(bf_hi(w4.w), hreg[j * 8 + 7], s7);
            }
            float s = ((s0 + s1) + (s2 + s3)) + ((s4 + s5) + (s6 + s7));
            #pragma unroll
            for (int o = 16; o; o >>= 1) s += __shfl_xor_sync(0xffffffffu, s, o);
            if (lane == 0) red[r0 + r] = s;
        }
        __syncthreads();   // red[] complete

        // ---- warp 0: gates + publish + two-level barrier ----
        if (wid == 0) {
            if (lane < PER) {
                const float hr = red[lane], hz = red[PER + lane], hn = red[2 * PER + lane];
                const float reset  = fsig(gr + hr);
                const float update = fsig(gz + hz);
                const float nv = ftanh(gn + reset * (hn + bnv));
                const float hnext = (1.f - update) * nv + update * h_s[base + lane];
                __stcg(out + (size_t)t * H + base + lane, hnext);
                lastv = hnext;
            }
            __syncwarp();                       // warp-scope ordering of lanes' stores
            if (lane == 0) {
                __threadfence();                // cumulative release of h_t stores
                // level 1: arrive at own group counter (8-way contention)
                atomicAdd(&g_grp[grp * 32], 1u);
                if (gleader) {
                    // leader: wait for own group (single fixed line), then root
                    const unsigned gt = (unsigned)(t + 1) * 8u;
                    while (*((volatile unsigned int*)&g_grp[grp * 32]) < gt) { }
                    __threadfence();            // cumulativity: group h_t before root
                    atomicAdd(&g_bar, 1u);
                }
                // all CTAs: wait on the single root line (PROVEN spin)
                const unsigned target = (unsigned)(t + 1) * 16u;
                while (*((volatile unsigned int*)&g_bar) < target) { }
                __threadfence();                // cumulative acquire
            }
            __syncwarp();
        }
        __syncthreads();   // propagate acquire CTA-wide; release into step t+1
    }

    if (tid < PER) out[(size_t)SEQ * H + base + tid] = lastv;
}

// ---------------- launch -----------------------------------------------------
extern "C" void kernel_launch(void* const* d_in, const int* in_sizes, int n_in,
                              void* d_out, int out_size)
{
    const float* xs         = (const float*)d_in[0];
    const float* init_state = (const float*)d_in[1];
    const float* Wi         = (const float*)d_in[2];
    const float* Wh         = (const float*)d_in[3];
    const float* bi         = (const float*)d_in[4];
    const float* bn         = (const float*)d_in[5];
    float* out = (float*)d_out;

    init_bar_kernel<<<1, 1>>>();

    dim3 ggrid(G3 / TN, SEQ / TM);     // (48, 32)
    igates_gemm<<<ggrid, 256>>>(xs, Wi, bi);

    const size_t smem = (size_t)NROWS * (H / 2) * sizeof(unsigned)   // weights
                      + (size_t)H * sizeof(float)                     // h stage
                      + NROWS * sizeof(float);                        // red
    cudaFuncSetAttribute(gru_recur, cudaFuncAttributeMaxDynamicSharedMemorySize,
                         (int)smem);
    gru_recur<<<NCTA, RTH, smem>>>(init_state, Wh, bn, out);
}

// round 16
// speedup vs baseline: 1.2719x; 1.2719x over previous
#include <cuda_runtime.h>
#include <cuda_bf16.h>
#include <cstdint>
#include <math.h>

#define SEQ 4096
#define H 2048
#define IN_DIM 2048
#define G3 6144

// ---------------- scratch ---------------------------------------------------
__device__ float g_igates[(size_t)SEQ * G3];   // ~100.7 MB
__device__ unsigned int g_bar;

__global__ void init_bar_kernel() { g_bar = 0u; }

// ---------------- tf32 mma helpers ------------------------------------------
__device__ __forceinline__ unsigned f2tf32(float f) {
    unsigned u;
    asm("cvt.rna.tf32.f32 %0, %1;" : "=r"(u) : "f"(f));
    return u;
}
__device__ __forceinline__ void mma_tf32(float* c, const unsigned* a,
                                         const unsigned* b) {
    asm volatile(
        "mma.sync.aligned.m16n8k8.row.col.f32.tf32.tf32.f32 "
        "{%0,%1,%2,%3}, {%4,%5,%6,%7}, {%8,%9}, {%0,%1,%2,%3};\n"
        : "+f"(c[0]), "+f"(c[1]), "+f"(c[2]), "+f"(c[3])
        : "r"(a[0]), "r"(a[1]), "r"(a[2]), "r"(a[3]), "r"(b[0]), "r"(b[1]));
}

// ---------------- Kernel 1: igates = xs @ Wi^T + bi ------------------------
// tf32 tensor cores + register-prefetch double buffering (1 sync per K-tile).
#define TM 128
#define TN 128
#define TK 16
#define NT (IN_DIM / TK)    // 128 K-tiles

__global__ __launch_bounds__(256) void igates_gemm(
    const float* __restrict__ A,
    const float* __restrict__ B,
    const float* __restrict__ bias)
{
    __shared__ unsigned As[2][TM][TK + 1];   // 17.0 KB
    __shared__ unsigned Bs[2][TN][TK + 1];   // 17.0 KB

    const int tid  = threadIdx.x;
    const int lane = tid & 31;
    const int wid  = tid >> 5;
    const int mw   = wid & 3;
    const int nw   = wid >> 2;
    const int bm   = blockIdx.y * TM;
    const int bn   = blockIdx.x * TN;
    const int grp  = lane >> 2;
    const int tig  = lane & 3;

    // per-thread loader coords: 2 float4 per matrix per tile
    int lrow[2], lcol[2];
    #pragma unroll
    for (int i = 0; i < 2; i++) {
        const int id = tid + i * 256;
        lrow[i] = id >> 2;
        lcol[i] = (id & 3) * 4;
    }

    float c[16][4];
    #pragma unroll
    for (int i = 0; i < 16; i++)
        #pragma unroll
        for (int j = 0; j < 4; j++) c[i][j] = 0.f;

    // prefetch tile 0 into registers
    float4 pa[2], pb[2];
    #pragma unroll
    for (int i = 0; i < 2; i++) {
        pa[i] = *(const float4*)(A + (size_t)(bm + lrow[i]) * IN_DIM + lcol[i]);
        pb[i] = *(const float4*)(B + (size_t)(bn + lrow[i]) * IN_DIM + lcol[i]);
    }

    for (int kt = 0; kt < NT; kt++) {
        const int buf = kt & 1;

        // convert + store the prefetched tile
        #pragma unroll
        for (int i = 0; i < 2; i++) {
            As[buf][lrow[i]][lcol[i] + 0] = f2tf32(pa[i].x);
            As[buf][lrow[i]][lcol[i] + 1] = f2tf32(pa[i].y);
            As[buf][lrow[i]][lcol[i] + 2] = f2tf32(pa[i].z);
            As[buf][lrow[i]][lcol[i] + 3] = f2tf32(pa[i].w);
            Bs[buf][lrow[i]][lcol[i] + 0] = f2tf32(pb[i].x);
            Bs[buf][lrow[i]][lcol[i] + 1] = f2tf32(pb[i].y);
            Bs[buf][lrow[i]][lcol[i] + 2] = f2tf32(pb[i].z);
            Bs[buf][lrow[i]][lcol[i] + 3] = f2tf32(pb[i].w);
        }
        __syncthreads();

        // prefetch next tile while computing this one
        if (kt + 1 < NT) {
            const int k0 = (kt + 1) * TK;
            #pragma unroll
            for (int i = 0; i < 2; i++) {
                pa[i] = *(const float4*)(A + (size_t)(bm + lrow[i]) * IN_DIM + k0 + lcol[i]);
                pb[i] = *(const float4*)(B + (size_t)(bn + lrow[i]) * IN_DIM + k0 + lcol[i]);
            }
        }

        #pragma unroll
        for (int kk = 0; kk < TK; kk += 8) {
            unsigned af[2][4];
            #pragma unroll
            for (int mi = 0; mi < 2; mi++) {
                const int r = mw * 32 + mi * 16 + grp;
                af[mi][0] = As[buf][r][kk + tig];
                af[mi][1] = As[buf][r + 8][kk + tig];
                af[mi][2] = As[buf][r][kk + tig + 4];
                af[mi][3] = As[buf][r + 8][kk + tig + 4];
            }
            #pragma unroll
            for (int ni = 0; ni < 8; ni++) {
                const int n = nw * 64 + ni * 8 + grp;
                unsigned bf[2];
                bf[0] = Bs[buf][n][kk + tig];
                bf[1] = Bs[buf][n][kk + tig + 4];
                mma_tf32(c[ni], af[0], bf);
                mma_tf32(c[8 + ni], af[1], bf);
            }
        }
        // no second sync: next iter writes the OTHER buffer, whose last
        // readers finished before this iteration's top sync.
    }

    #pragma unroll
    for (int mi = 0; mi < 2; mi++) {
        #pragma unroll
        for (int ni = 0; ni < 8; ni++) {
            const float* cf = c[mi * 8 + ni];
            const int row = bm + mw * 32 + mi * 16 + grp;
            const int col = bn + nw * 64 + ni * 8 + 2 * tig;
            const float b0 = bias[col], b1 = bias[col + 1];
            float2 v01; v01.x = cf[0] + b0; v01.y = cf[1] + b1;
            float2 v23; v23.x = cf[2] + b0; v23.y = cf[3] + b1;
            *(float2*)(g_igates + (size_t)row * G3 + col) = v01;
            *(float2*)(g_igates + (size_t)(row + 8) * G3 + col) = v23;
        }
    }
}

// ---------------- Kernel 2: persistent GRU recurrence (R13 EXACT) ----------
#define NCTA 128
#define PER 16
#define NROWS 48
#define RTH 256

__device__ __forceinline__ float bf_lo(unsigned w) {
    return __uint_as_float(w << 16);
}
__device__ __forceinline__ float bf_hi(unsigned w) {
    return __uint_as_float(w & 0xFFFF0000u);
}
__device__ __forceinline__ float fsig(float x) {
    return __fdividef(1.f, 1.f + __expf(-x));
}
__device__ __forceinline__ float ftanh(float x) {
    return __fdividef(2.f, 1.f + __expf(-2.f * x)) - 1.f;
}

__global__ __launch_bounds__(RTH, 1) void gru_recur(
    const float* __restrict__ init_state,
    const float* __restrict__ Wh,
    const float* __restrict__ bn,
    float* __restrict__ out)
{
    extern __shared__ float smem[];
    unsigned* wc = (unsigned*)smem;                        // NROWS * H/2 words (192KB)
    float* h_s   = (float*)(wc + (size_t)NROWS * (H/2));   // H floats (8KB)
    float* red   = h_s + H;                                // NROWS floats

    const int tid  = threadIdx.x;
    const int lane = tid & 31;
    const int wid  = tid >> 5;
    const int base = blockIdx.x * PER;
    const int r0   = wid * 6;            // this warp's 6 rows

    // prologue: convert+cache 48 Wh rows as packed bf16 (lo=elem 2v, hi=2v+1)
    for (int r = 0; r < NROWS; r++) {
        const int gate = r / PER, i = r % PER;
        const float2* src = (const float2*)(Wh + (size_t)(gate * H + base + i) * H);
        unsigned* dst = wc + (size_t)r * (H / 2);
        for (int v = tid; v < H / 2; v += RTH) {
            float2 w = src[v];
            __nv_bfloat162 b2 = __floats2bfloat162_rn(w.x, w.y);
            dst[v] = *(unsigned*)&b2;
        }
    }
    __syncthreads();   // order prologue wc writes vs first-step reads

    float bnv = 0.f, lastv = 0.f;
    if (tid < PER) bnv = bn[base + tid];

    for (int t = 0; t < SEQ; t++) {
        const float* hprev = (t == 0) ? init_state : (out + (size_t)(t - 1) * H);

        // early reads: igates (DRAM); consumed in the epilogue
        float gr = 0.f, gz = 0.f, gn = 0.f;
        if (tid < PER) {
            const float* ig = g_igates + (size_t)t * G3;
            gr = ig[base + tid];
            gz = ig[H + base + tid];
            gn = ig[2 * H + base + tid];
        }

        // ---- stage h_{t-1} into SMEM once per CTA (one 8KB L2 read) ----
        {
            const float4* h4 = (const float4*)hprev;
            float4* d4 = (float4*)h_s;
            d4[tid]       = __ldcg(h4 + tid);
            d4[tid + RTH] = __ldcg(h4 + tid + RTH);
        }
        __syncthreads();

        // ---- copy h from SMEM into registers once per warp ----
        float hreg[64];
        {
            const float4* hs4 = (const float4*)h_s;
            #pragma unroll
            for (int j = 0; j < 8; j++) {
                float4 a = hs4[(j * 32 + lane) * 2 + 0];
                float4 b = hs4[(j * 32 + lane) * 2 + 1];
                hreg[j * 8 + 0] = a.x; hreg[j * 8 + 1] = a.y;
                hreg[j * 8 + 2] = a.z; hreg[j * 8 + 3] = a.w;
                hreg[j * 8 + 4] = b.x; hreg[j * 8 + 5] = b.y;
                hreg[j * 8 + 6] = b.z; hreg[j * 8 + 7] = b.w;
            }
        }

        // ---- 6 dot products per warp (weights from SMEM, h from regs) ----
        #pragma unroll
        for (int r = 0; r < 6; r++) {
            const uint4* wp = (const uint4*)(wc + (size_t)(r0 + r) * (H / 2));
            float s0 = 0.f, s1 = 0.f, s2 = 0.f, s3 = 0.f;
            float s4 = 0.f, s5 = 0.f, s6 = 0.f, s7 = 0.f;
            #pragma unroll
            for (int j = 0; j < 8; j++) {
                uint4 w4 = wp[j * 32 + lane];       // 8 bf16 = h elems [8j..8j+7]
                s0 = fmaf(bf_lo(w4.x), hreg[j * 8 + 0], s0);
                s1 = fmaf(bf_hi(w4.x), hreg[j * 8 + 1], s1);
                s2 = fmaf(bf_lo(w4.y), hreg[j * 8 + 2], s2);
                s3 = fmaf(bf_hi(w4.y), hreg[j * 8 + 3], s3);
                s4 = fmaf(bf_lo(w4.z), hreg[j * 8 + 4], s4);
                s5 = fmaf(bf_hi(w4.z), hreg[j * 8 + 5], s5);
                s6 = fmaf(bf_lo(w4.w), hreg[j * 8 + 6], s6);
                s7 = fmaf(bf_hi(w4.w), hreg[j * 8 + 7], s7);
            }
            float s = ((s0 + s1) + (s2 + s3)) + ((s4 + s5) + (s6 + s7));
            #pragma unroll
            for (int o = 16; o; o >>= 1) s += __shfl_xor_sync(0xffffffffu, s, o);
            if (lane == 0) red[r0 + r] = s;
        }
        __syncthreads();   // red[] complete

        // ---- warp 0: gates + publish + barrier (FROZEN proven shape) ----
        if (wid == 0) {
            if (lane < PER) {
                const float hr = red[lane], hz = red[PER + lane], hn = red[2 * PER + lane];
                const float reset  = fsig(gr + hr);
                const float update = fsig(gz + hz);
                const float nv = ftanh(gn + reset * (hn + bnv));
                const float hnext = (1.f - update) * nv + update * h_s[base + lane];
                __stcg(out + (size_t)t * H + base + lane, hnext);
                lastv = hnext;
            }
            __syncwarp();                       // warp-scope ordering of lanes' stores
            if (lane == 0) {
                __threadfence();                // cumulative release (covers lanes 0-15)
                atomicAdd(&g_bar, 1u);
                const unsigned target = (unsigned)(t + 1) * NCTA;
                while (*((volatile unsigned int*)&g_bar) < target) { }
                __threadfence();                // cumulative acquire
            }
            __syncwarp();
        }
        __syncthreads();   // propagate acquire CTA-wide; release into step t+1
    }

    if (tid < PER) out[(size_t)SEQ * H + base + tid] = lastv;
}

// ---------------- launch -----------------------------------------------------
extern "C" void kernel_launch(void* const* d_in, const int* in_sizes, int n_in,
                              void* d_out, int out_size)
{
    const float* xs         = (const float*)d_in[0];
    const float* init_state = (const float*)d_in[1];
    const float* Wi         = (const float*)d_in[2];
    const float* Wh         = (const float*)d_in[3];
    const float* bi         = (const float*)d_in[4];
    const float* bn         = (const float*)d_in[5];
    float* out = (float*)d_out;

    init_bar_kernel<<<1, 1>>>();

    dim3 ggrid(G3 / TN, SEQ / TM);     // (48, 32)
    igates_gemm<<<ggrid, 256>>>(xs, Wi, bi);

    const size_t smem = (size_t)NROWS * (H / 2) * sizeof(unsigned)   // weights
                      + (size_t)H * sizeof(float)                     // h stage
                      + NROWS * sizeof(float);                        // red
    cudaFuncSetAttribute(gru_recur, cudaFuncAttributeMaxDynamicSharedMemorySize,
                         (int)smem);
    gru_recur<<<NCTA, RTH, smem>>>(init_state, Wh, bn, out);
}